// round 10
// baseline (speedup 1.0000x reference)
#include <cuda_runtime.h>
#include <math.h>
#include <stdint.h>

#define BATCH   8
#define NPTS    4096
#define CFEAT   64
#define HID     128
#define NPOINT  1024
#define NSAMP   32

// scratch: group indices (set of 32 neighbor indices per centroid)
__device__ int g_gidx[BATCH * NPOINT * NSAMP];

// interleaved (k-pair, col, 2) weights for FFMA2 path
// layer pair-counts: 34 (K=67), 64 (K=128), 66 (K=131), 64 (K=128)
#define K2_1 34
#define K2_2 64
#define K2_3 66
#define K2_4 64
#define WPO1 0
#define WPO2 (K2_1 * 256)                 // 8704
#define WPO3 (WPO2 + K2_2 * 256)          // 25088
#define WPO4 (WPO3 + K2_3 * 256)          // 41984
#define WPTOT (WPO4 + K2_4 * 256)         // 58368
__device__ float g_wp[WPTOT];

// exact (non-fused) squared distance, matching XLA elementwise mul + ((s0+s1)+s2) reduce
__device__ __forceinline__ float sqdist(float ax, float ay, float az,
                                        float bx, float by, float bz) {
    float dx = ax - bx, dy = ay - by, dz = az - bz;
    return __fadd_rn(__fadd_rn(__fmul_rn(dx, dx), __fmul_rn(dy, dy)),
                     __fmul_rn(dz, dz));
}

__device__ __forceinline__ unsigned long long fma2(unsigned long long a,
                                                   unsigned long long b,
                                                   unsigned long long c) {
    unsigned long long d;
    asm("fma.rn.f32x2 %0, %1, %2, %3;" : "=l"(d) : "l"(a), "l"(b), "l"(c));
    return d;
}

// ---------------------------------------------------------------------------
// Kernel 0: interleave weights: wp[k2*256 + c*2 + {0,1}] = W[2k2][c], W[2k2+1][c]
// ---------------------------------------------------------------------------
__global__ void prep_kernel(const float* __restrict__ W1f, const float* __restrict__ W2f,
                            const float* __restrict__ W1w, const float* __restrict__ W2w)
{
    int i = blockIdx.x * blockDim.x + threadIdx.x;
    if (i >= (K2_1 + K2_2 + K2_3 + K2_4) * 128) return;
    int k2g = i >> 7, c = i & 127;
    const float* W; int K, off, k2;
    if (k2g < K2_1)                { W = W1f; K = 67;  off = WPO1; k2 = k2g; }
    else if (k2g < K2_1 + K2_2)    { W = W2f; K = 128; off = WPO2; k2 = k2g - K2_1; }
    else if (k2g < K2_1+K2_2+K2_3) { W = W1w; K = 131; off = WPO3; k2 = k2g - K2_1 - K2_2; }
    else                           { W = W2w; K = 128; off = WPO4; k2 = k2g - K2_1 - K2_2 - K2_3; }
    g_wp[off + k2 * 256 + 2 * c]     = W[(2 * k2) * 128 + c];
    g_wp[off + k2 * 256 + 2 * c + 1] = (2 * k2 + 1 < K) ? W[(2 * k2 + 1) * 128 + c] : 0.f;
}

// ---------------------------------------------------------------------------
// Kernel 1: farthest point sampling (proven R4 form: 256 threads, 16 pts/thr,
// one barrier per step, redux-based argmax with first-occurrence ties).
// ---------------------------------------------------------------------------
__global__ __launch_bounds__(256) void fps_kernel(
    const float* __restrict__ xyz, float* __restrict__ newxyz)
{
    const int b = blockIdx.x;
    const float* X = xyz + b * NPTS * 3;
    const int t = threadIdx.x;
    const int w = t >> 5, lane = t & 31;

    __shared__ float s_x[NPTS], s_y[NPTS], s_z[NPTS];
    __shared__ unsigned s_wv[2][8];
    __shared__ unsigned s_wi[2][8];

    float px[16], py[16], pz[16], d[16];
#pragma unroll
    for (int j = 0; j < 16; j++) {
        int p = t + j * 256;
        px[j] = X[p * 3 + 0];
        py[j] = X[p * 3 + 1];
        pz[j] = X[p * 3 + 2];
        s_x[p] = px[j]; s_y[p] = py[j]; s_z[p] = pz[j];
    }
    if (t == 0) {
        newxyz[(b * NPOINT + 0) * 3 + 0] = X[0];
        newxyz[(b * NPOINT + 0) * 3 + 1] = X[1];
        newxyz[(b * NPOINT + 0) * 3 + 2] = X[2];
    }
    __syncthreads();
    {
        const float cx = s_x[0], cy = s_y[0], cz = s_z[0];
#pragma unroll
        for (int j = 0; j < 16; j++) d[j] = sqdist(px[j], py[j], pz[j], cx, cy, cz);
    }

    for (int s = 1; s < NPOINT; s++) {
        const int par = s & 1;
        float m = d[0];
#pragma unroll
        for (int j = 1; j < 16; j++) m = fmaxf(m, d[j]);
        unsigned wm = __reduce_max_sync(0xffffffffu, __float_as_uint(m));
        unsigned cand = 0xffffffffu;
#pragma unroll
        for (int j = 0; j < 16; j++) {
            if (__float_as_uint(d[j]) == wm) cand = min(cand, (unsigned)(t + j * 256));
        }
        unsigned wi = __reduce_min_sync(0xffffffffu, cand);
        if (lane == 0) { s_wv[par][w] = wm; s_wi[par][w] = wi; }
        __syncthreads();
        unsigned bv = s_wv[par][0], bi = s_wi[par][0];
#pragma unroll
        for (int w2 = 1; w2 < 8; w2++) {
            unsigned v = s_wv[par][w2], i2 = s_wi[par][w2];
            if (v > bv || (v == bv && i2 < bi)) { bv = v; bi = i2; }
        }
        const float cx = s_x[bi], cy = s_y[bi], cz = s_z[bi];
        if (t == 0) {
            newxyz[(b * NPOINT + s) * 3 + 0] = cx;
            newxyz[(b * NPOINT + s) * 3 + 1] = cy;
            newxyz[(b * NPOINT + s) * 3 + 2] = cz;
        }
#pragma unroll
        for (int j = 0; j < 16; j++) {
            float nd = sqdist(px[j], py[j], pz[j], cx, cy, cz);
            d[j] = fminf(d[j], nd);
        }
    }
}

// ---------------------------------------------------------------------------
// Kernel 2: ball query. One block per centroid; correct SET of 32 smallest
// by (masked d2, index) with stable inf-padding semantics.
// ---------------------------------------------------------------------------
__global__ __launch_bounds__(256) void group_kernel(
    const float* __restrict__ xyz, const float* __restrict__ newxyz)
{
    const int cid = blockIdx.x;          // b*1024 + s
    const int b = cid >> 10;
    const float* X = xyz + b * NPTS * 3;
    const int tid = threadIdx.x;

    __shared__ float s_v[NPTS];
    __shared__ int   s_i[NPTS];
    __shared__ int   s_cnt;
    if (tid == 0) s_cnt = 0;
    __syncthreads();

    const float R2 = 0.0225f;  // f32 round of python 0.15**2
    const float cx = newxyz[cid * 3 + 0];
    const float cy = newxyz[cid * 3 + 1];
    const float cz = newxyz[cid * 3 + 2];

    for (int p = tid; p < NPTS; p += 256) {
        float dd = sqdist(X[p * 3], X[p * 3 + 1], X[p * 3 + 2], cx, cy, cz);
        if (dd <= R2) {
            int pos = atomicAdd(&s_cnt, 1);
            s_v[pos] = dd; s_i[pos] = p;
        }
    }
    __syncthreads();
    const int M = s_cnt;
    int* out = g_gidx + cid * NSAMP;

    if (M >= NSAMP) {
        for (int e = tid; e < M; e += 256) {
            float v = s_v[e]; int i = s_i[e];
            int rank = 0;
            for (int j = 0; j < M; j++) {
                float vj = s_v[j]; int ij = s_i[j];
                rank += (vj < v) || (vj == v && ij < i);
            }
            if (rank < NSAMP) out[rank] = i;
        }
    } else {
        if (tid < M) {
            float v = s_v[tid]; int i = s_i[tid];
            int rank = 0;
            for (int j = 0; j < M; j++) {
                float vj = s_v[j]; int ij = s_i[j];
                rank += (vj < v) || (vj == v && ij < i);
            }
            out[rank] = i;
        }
        // inf entries in stable (ascending index) order
        if (tid == 0) {
            int k = M;
            for (int p = 0; p < NPTS && k < NSAMP; p++) {
                float dd = sqdist(X[p * 3], X[p * 3 + 1], X[p * 3 + 2], cx, cy, cz);
                if (!(dd <= R2)) out[k++] = p;
            }
        }
    }
}

// ---------------------------------------------------------------------------
// Kernel 3: per-centroid MLP chain — exact R3 loop shape (proven 745us at
// 4 CTAs/SM), with __launch_bounds__(128,5) forcing <=102 regs -> 5 CTAs/SM.
// Live set is ~90 regs (64 acc + 8 weight + 2 act + addressing), so the cap
// costs only scheduling headroom. FMA2 order identical -> same rel_err.
// ---------------------------------------------------------------------------
#define LDA 132   // padded leading dim (16B-aligned row stride)

// C[32x128] = act( A[32x2K2] @ Wp + bias ); sOut may alias sA (internal bar).
__device__ __forceinline__ void gemm_tile2(
    const float* __restrict__ sA, int lda, int K2,
    const float* __restrict__ Wp, const float* __restrict__ bias,
    float* __restrict__ sOut, int ldOut, int relu, int tx, int ty)
{
    unsigned long long acc[8][4];
#pragma unroll
    for (int i = 0; i < 8; i++)
#pragma unroll
        for (int j = 0; j < 4; j++) acc[i][j] = 0ull;

    const int c0 = tx * 4;
    for (int k2 = 0; k2 < K2; k2++) {
        ulonglong2 wva = *(const ulonglong2*)(Wp + k2 * 256 + c0 * 2);
        ulonglong2 wvb = *(const ulonglong2*)(Wp + k2 * 256 + c0 * 2 + 4);
#pragma unroll
        for (int i = 0; i < 8; i++) {
            unsigned long long ap =
                *(const unsigned long long*)(sA + (ty * 8 + i) * lda + 2 * k2);
            acc[i][0] = fma2(ap, wva.x, acc[i][0]);
            acc[i][1] = fma2(ap, wva.y, acc[i][1]);
            acc[i][2] = fma2(ap, wvb.x, acc[i][2]);
            acc[i][3] = fma2(ap, wvb.y, acc[i][3]);
        }
    }
    float4 bb = *(const float4*)(bias + c0);
    __syncthreads();   // all reads of sA done -> in-place store is safe
#pragma unroll
    for (int i = 0; i < 8; i++) {
        float v[4];
#pragma unroll
        for (int j = 0; j < 4; j++) {
            unsigned long long a = acc[i][j];
            v[j] = __uint_as_float((unsigned)a) + __uint_as_float((unsigned)(a >> 32));
        }
        float v0 = v[0] + bb.x, v1 = v[1] + bb.y, v2 = v[2] + bb.z, v3 = v[3] + bb.w;
        if (relu) {
            v0 = fmaxf(v0, 0.f); v1 = fmaxf(v1, 0.f);
            v2 = fmaxf(v2, 0.f); v3 = fmaxf(v3, 0.f);
        }
        float* o = sOut + (ty * 8 + i) * ldOut + c0;
        o[0] = v0; o[1] = v1; o[2] = v2; o[3] = v3;
    }
}

__global__ __launch_bounds__(128, 5) void mlp_kernel(
    const float* __restrict__ xyz, const float* __restrict__ feats,
    const float* __restrict__ newxyz,
    const float* __restrict__ b1f, const float* __restrict__ b2f,
    const float* __restrict__ b1w, const float* __restrict__ b2w,
    float* __restrict__ fout)
{
    __shared__ float s_a[32 * LDA];    // f_in -> w_in -> h2 (in-place) -> partials
    __shared__ float s_h[32 * 128];    // h1 -> f_prime (in-place)
    __shared__ float s_mean[128];
    __shared__ int   s_g[32];

    const int cid = blockIdx.x;
    const int b = cid >> 10;
    const int tid = threadIdx.x;
    const int tx = tid & 31, ty = tid >> 5;

    if (tid < 32) s_g[tid] = g_gidx[cid * NSAMP + tid];
    __syncthreads();

    const float cx = newxyz[cid * 3 + 0];
    const float cy = newxyz[cid * 3 + 1];
    const float cz = newxyz[cid * 3 + 2];

    if (tid < 32) {
        int g = s_g[tid];
        const float* p = xyz + (b * NPTS + g) * 3;
        s_a[tid * LDA + 0] = p[0] - cx;
        s_a[tid * LDA + 1] = p[1] - cy;
        s_a[tid * LDA + 2] = p[2] - cz;
        s_a[tid * LDA + 67]  = 0.f;    // zero pad col for K=67 pair loop
        s_a[tid * LDA + 131] = 0.f;    // zero pad col for K=131 pair loop
    }
    for (int m = tid; m < 32 * CFEAT; m += 128) {
        int r = m >> 6, c = m & 63;
        s_a[r * LDA + 3 + c] = feats[(b * NPTS + s_g[r]) * CFEAT + c];
    }
    __syncthreads();

    // h1 = relu(f_in @ W1f + b1f)          (s_a -> s_h)
    gemm_tile2(s_a, LDA, K2_1, g_wp + WPO1, b1f, s_h, 128, 1, tx, ty);
    __syncthreads();
    // f' = relu(h1 @ W2f + b2f)            (s_h -> s_h, in place)
    gemm_tile2(s_h, 128, K2_2, g_wp + WPO2, b2f, s_h, 128, 1, tx, ty);
    __syncthreads();

    // mean over the 32 samples
    {
        float sum = 0.f;
        for (int r = 0; r < 32; r++) sum += s_h[r * 128 + tid];
        s_mean[tid] = sum * (1.0f / 32.0f);
    }
    __syncthreads();
    // w_in = [dxyz | f' - mean]  (dxyz already in cols 0..2, col 131 = 0)
    for (int m = tid; m < 32 * 128; m += 128) {
        int r = m >> 7, c = m & 127;
        s_a[r * LDA + 3 + c] = s_h[r * 128 + c] - s_mean[c];
    }
    __syncthreads();

    // h2 = relu(w_in @ W1w + b1w)          (s_a -> s_a, in place)
    gemm_tile2(s_a, LDA, K2_3, g_wp + WPO3, b1w, s_a, LDA, 1, tx, ty);
    __syncthreads();

    // final GEMM + sigmoid + weighted sum fused: alpha = sigmoid(h2 @ W2w + b2w)
    unsigned long long acc[8][4];
#pragma unroll
    for (int i = 0; i < 8; i++)
#pragma unroll
        for (int j = 0; j < 4; j++) acc[i][j] = 0ull;
    const int c0 = tx * 4;
    const float* Wp4 = g_wp + WPO4;
    for (int k2 = 0; k2 < K2_4; k2++) {
        ulonglong2 wva = *(const ulonglong2*)(Wp4 + k2 * 256 + c0 * 2);
        ulonglong2 wvb = *(const ulonglong2*)(Wp4 + k2 * 256 + c0 * 2 + 4);
#pragma unroll
        for (int i = 0; i < 8; i++) {
            unsigned long long ap =
                *(const unsigned long long*)(s_a + (ty * 8 + i) * LDA + 2 * k2);
            acc[i][0] = fma2(ap, wva.x, acc[i][0]);
            acc[i][1] = fma2(ap, wva.y, acc[i][1]);
            acc[i][2] = fma2(ap, wvb.x, acc[i][2]);
            acc[i][3] = fma2(ap, wvb.y, acc[i][3]);
        }
    }
    float4 bb = *(const float4*)(b2w + c0);
    float part0 = 0.f, part1 = 0.f, part2 = 0.f, part3 = 0.f;
#pragma unroll
    for (int i = 0; i < 8; i++) {
        int r = ty * 8 + i;
        float z[4];
#pragma unroll
        for (int j = 0; j < 4; j++) {
            unsigned long long a = acc[i][j];
            z[j] = __uint_as_float((unsigned)a) + __uint_as_float((unsigned)(a >> 32));
        }
        float a0 = 1.0f / (1.0f + __expf(-(z[0] + bb.x)));
        float a1 = 1.0f / (1.0f + __expf(-(z[1] + bb.y)));
        float a2 = 1.0f / (1.0f + __expf(-(z[2] + bb.z)));
        float a3 = 1.0f / (1.0f + __expf(-(z[3] + bb.w)));
        part0 += a0 * s_h[r * 128 + c0 + 0];
        part1 += a1 * s_h[r * 128 + c0 + 1];
        part2 += a2 * s_h[r * 128 + c0 + 2];
        part3 += a3 * s_h[r * 128 + c0 + 3];
    }
    // reduce the 4 warps' partials (reuse s_a; sync before overwrite)
    __syncthreads();
    float* s_part = s_a;
    s_part[ty * 128 + c0 + 0] = part0;
    s_part[ty * 128 + c0 + 1] = part1;
    s_part[ty * 128 + c0 + 2] = part2;
    s_part[ty * 128 + c0 + 3] = part3;
    __syncthreads();
    if (ty == 0) {
        float4 o;
        o.x = s_part[c0 + 0] + s_part[128 + c0 + 0] + s_part[256 + c0 + 0] + s_part[384 + c0 + 0];
        o.y = s_part[c0 + 1] + s_part[128 + c0 + 1] + s_part[256 + c0 + 1] + s_part[384 + c0 + 1];
        o.z = s_part[c0 + 2] + s_part[128 + c0 + 2] + s_part[256 + c0 + 2] + s_part[384 + c0 + 2];
        o.w = s_part[c0 + 3] + s_part[128 + c0 + 3] + s_part[256 + c0 + 3] + s_part[384 + c0 + 3];
        *(float4*)(fout + cid * 128 + c0) = o;
    }
}

// ---------------------------------------------------------------------------

extern "C" void kernel_launch(void* const* d_in, const int* in_sizes, int n_in,
                              void* d_out, int out_size)
{
    const float* xyz   = (const float*)d_in[0];
    const float* feats = (const float*)d_in[1];
    const float* W1f   = (const float*)d_in[2];
    const float* b1f   = (const float*)d_in[3];
    const float* W2f   = (const float*)d_in[4];
    const float* b2f   = (const float*)d_in[5];
    const float* W1w   = (const float*)d_in[6];
    const float* b1w   = (const float*)d_in[7];
    const float* W2w   = (const float*)d_in[8];
    const float* b2w   = (const float*)d_in[9];

    float* out    = (float*)d_out;
    float* newxyz = out;                         // (B, NPOINT, 3)
    float* fout   = out + BATCH * NPOINT * 3;    // (B, NPOINT, HID)

    prep_kernel<<<(228 * 128 + 255) / 256, 256>>>(W1f, W2f, W1w, W2w);
    fps_kernel<<<BATCH, 256>>>(xyz, newxyz);
    group_kernel<<<BATCH * NPOINT, 256>>>(xyz, newxyz);
    mlp_kernel<<<BATCH * NPOINT, 128>>>(
        xyz, feats, newxyz, b1f, b2f, b1w, b2w, fout);
}

// round 13
// speedup vs baseline: 1.3876x; 1.3876x over previous
#include <cuda_runtime.h>
#include <math.h>
#include <stdint.h>

#define BATCH   8
#define NPTS    4096
#define CFEAT   64
#define HID     128
#define NPOINT  1024
#define NSAMP   32

// scratch: group indices (set of 32 neighbor indices per centroid)
__device__ int g_gidx[BATCH * NPOINT * NSAMP];

// interleaved (k-pair, col, 2) weights for FFMA2 path
// layer pair-counts: 34 (K=67), 64 (K=128), 66 (K=131), 64 (K=128)
#define K2_1 34
#define K2_2 64
#define K2_3 66
#define K2_4 64
#define WPO1 0
#define WPO2 (K2_1 * 256)                 // 8704
#define WPO3 (WPO2 + K2_2 * 256)          // 25088
#define WPO4 (WPO3 + K2_3 * 256)          // 41984
#define WPTOT (WPO4 + K2_4 * 256)         // 58368
__device__ float g_wp[WPTOT];

// exact (non-fused) squared distance, matching XLA elementwise mul + ((s0+s1)+s2) reduce
__device__ __forceinline__ float sqdist(float ax, float ay, float az,
                                        float bx, float by, float bz) {
    float dx = ax - bx, dy = ay - by, dz = az - bz;
    return __fadd_rn(__fadd_rn(__fmul_rn(dx, dx), __fmul_rn(dy, dy)),
                     __fmul_rn(dz, dz));
}

__device__ __forceinline__ unsigned long long fma2(unsigned long long a,
                                                   unsigned long long b,
                                                   unsigned long long c) {
    unsigned long long d;
    asm("fma.rn.f32x2 %0, %1, %2, %3;" : "=l"(d) : "l"(a), "l"(b), "l"(c));
    return d;
}

// ---------------------------------------------------------------------------
// Kernel 0: interleave weights: wp[k2*256 + c*2 + {0,1}] = W[2k2][c], W[2k2+1][c]
// ---------------------------------------------------------------------------
__global__ void prep_kernel(const float* __restrict__ W1f, const float* __restrict__ W2f,
                            const float* __restrict__ W1w, const float* __restrict__ W2w)
{
    int i = blockIdx.x * blockDim.x + threadIdx.x;
    if (i >= (K2_1 + K2_2 + K2_3 + K2_4) * 128) return;
    int k2g = i >> 7, c = i & 127;
    const float* W; int K, off, k2;
    if (k2g < K2_1)                { W = W1f; K = 67;  off = WPO1; k2 = k2g; }
    else if (k2g < K2_1 + K2_2)    { W = W2f; K = 128; off = WPO2; k2 = k2g - K2_1; }
    else if (k2g < K2_1+K2_2+K2_3) { W = W1w; K = 131; off = WPO3; k2 = k2g - K2_1 - K2_2; }
    else                           { W = W2w; K = 128; off = WPO4; k2 = k2g - K2_1 - K2_2 - K2_3; }
    g_wp[off + k2 * 256 + 2 * c]     = W[(2 * k2) * 128 + c];
    g_wp[off + k2 * 256 + 2 * c + 1] = (2 * k2 + 1 < K) ? W[(2 * k2 + 1) * 128 + c] : 0.f;
}

// ---------------------------------------------------------------------------
// Kernel 1: farthest point sampling (proven R4 form: 256 threads, 16 pts/thr,
// one barrier per step, redux-based argmax with first-occurrence ties).
// ---------------------------------------------------------------------------
__global__ __launch_bounds__(256) void fps_kernel(
    const float* __restrict__ xyz, float* __restrict__ newxyz)
{
    const int b = blockIdx.x;
    const float* X = xyz + b * NPTS * 3;
    const int t = threadIdx.x;
    const int w = t >> 5, lane = t & 31;

    __shared__ float s_x[NPTS], s_y[NPTS], s_z[NPTS];
    __shared__ unsigned s_wv[2][8];
    __shared__ unsigned s_wi[2][8];

    float px[16], py[16], pz[16], d[16];
#pragma unroll
    for (int j = 0; j < 16; j++) {
        int p = t + j * 256;
        px[j] = X[p * 3 + 0];
        py[j] = X[p * 3 + 1];
        pz[j] = X[p * 3 + 2];
        s_x[p] = px[j]; s_y[p] = py[j]; s_z[p] = pz[j];
    }
    if (t == 0) {
        newxyz[(b * NPOINT + 0) * 3 + 0] = X[0];
        newxyz[(b * NPOINT + 0) * 3 + 1] = X[1];
        newxyz[(b * NPOINT + 0) * 3 + 2] = X[2];
    }
    __syncthreads();
    {
        const float cx = s_x[0], cy = s_y[0], cz = s_z[0];
#pragma unroll
        for (int j = 0; j < 16; j++) d[j] = sqdist(px[j], py[j], pz[j], cx, cy, cz);
    }

    for (int s = 1; s < NPOINT; s++) {
        const int par = s & 1;
        float m = d[0];
#pragma unroll
        for (int j = 1; j < 16; j++) m = fmaxf(m, d[j]);
        unsigned wm = __reduce_max_sync(0xffffffffu, __float_as_uint(m));
        unsigned cand = 0xffffffffu;
#pragma unroll
        for (int j = 0; j < 16; j++) {
            if (__float_as_uint(d[j]) == wm) cand = min(cand, (unsigned)(t + j * 256));
        }
        unsigned wi = __reduce_min_sync(0xffffffffu, cand);
        if (lane == 0) { s_wv[par][w] = wm; s_wi[par][w] = wi; }
        __syncthreads();
        unsigned bv = s_wv[par][0], bi = s_wi[par][0];
#pragma unroll
        for (int w2 = 1; w2 < 8; w2++) {
            unsigned v = s_wv[par][w2], i2 = s_wi[par][w2];
            if (v > bv || (v == bv && i2 < bi)) { bv = v; bi = i2; }
        }
        const float cx = s_x[bi], cy = s_y[bi], cz = s_z[bi];
        if (t == 0) {
            newxyz[(b * NPOINT + s) * 3 + 0] = cx;
            newxyz[(b * NPOINT + s) * 3 + 1] = cy;
            newxyz[(b * NPOINT + s) * 3 + 2] = cz;
        }
#pragma unroll
        for (int j = 0; j < 16; j++) {
            float nd = sqdist(px[j], py[j], pz[j], cx, cy, cz);
            d[j] = fminf(d[j], nd);
        }
    }
}

// ---------------------------------------------------------------------------
// Kernel 2: ball query. One block per centroid; correct SET of 32 smallest
// by (masked d2, index) with stable inf-padding semantics.
// ---------------------------------------------------------------------------
__global__ __launch_bounds__(256) void group_kernel(
    const float* __restrict__ xyz, const float* __restrict__ newxyz)
{
    const int cid = blockIdx.x;          // b*1024 + s
    const int b = cid >> 10;
    const float* X = xyz + b * NPTS * 3;
    const int tid = threadIdx.x;

    __shared__ float s_v[NPTS];
    __shared__ int   s_i[NPTS];
    __shared__ int   s_cnt;
    if (tid == 0) s_cnt = 0;
    __syncthreads();

    const float R2 = 0.0225f;  // f32 round of python 0.15**2
    const float cx = newxyz[cid * 3 + 0];
    const float cy = newxyz[cid * 3 + 1];
    const float cz = newxyz[cid * 3 + 2];

    for (int p = tid; p < NPTS; p += 256) {
        float dd = sqdist(X[p * 3], X[p * 3 + 1], X[p * 3 + 2], cx, cy, cz);
        if (dd <= R2) {
            int pos = atomicAdd(&s_cnt, 1);
            s_v[pos] = dd; s_i[pos] = p;
        }
    }
    __syncthreads();
    const int M = s_cnt;
    int* out = g_gidx + cid * NSAMP;

    if (M >= NSAMP) {
        for (int e = tid; e < M; e += 256) {
            float v = s_v[e]; int i = s_i[e];
            int rank = 0;
            for (int j = 0; j < M; j++) {
                float vj = s_v[j]; int ij = s_i[j];
                rank += (vj < v) || (vj == v && ij < i);
            }
            if (rank < NSAMP) out[rank] = i;
        }
    } else {
        if (tid < M) {
            float v = s_v[tid]; int i = s_i[tid];
            int rank = 0;
            for (int j = 0; j < M; j++) {
                float vj = s_v[j]; int ij = s_i[j];
                rank += (vj < v) || (vj == v && ij < i);
            }
            out[rank] = i;
        }
        // inf entries in stable (ascending index) order
        if (tid == 0) {
            int k = M;
            for (int p = 0; p < NPTS && k < NSAMP; p++) {
                float dd = sqdist(X[p * 3], X[p * 3 + 1], X[p * 3 + 2], cx, cy, cz);
                if (!(dd <= R2)) out[k++] = p;
            }
        }
    }
}

// ---------------------------------------------------------------------------
// Kernel 3: per-centroid MLP chain — exact R3 form (proven mlp=745us:
// 128 threads, 8x4 tile, simple k2 loop, NO occupancy cap -> 128 regs,
// 4 CTAs/SM). FMA2 accumulation order identical to all passing rounds.
// ---------------------------------------------------------------------------
#define LDA 132   // padded leading dim (16B-aligned row stride)

// C[32x128] = act( A[32x2K2] @ Wp + bias ); sOut may alias sA (internal bar).
__device__ __forceinline__ void gemm_tile2(
    const float* __restrict__ sA, int lda, int K2,
    const float* __restrict__ Wp, const float* __restrict__ bias,
    float* __restrict__ sOut, int ldOut, int relu, int tx, int ty)
{
    unsigned long long acc[8][4];
#pragma unroll
    for (int i = 0; i < 8; i++)
#pragma unroll
        for (int j = 0; j < 4; j++) acc[i][j] = 0ull;

    const int c0 = tx * 4;
    for (int k2 = 0; k2 < K2; k2++) {
        ulonglong2 wva = *(const ulonglong2*)(Wp + k2 * 256 + c0 * 2);
        ulonglong2 wvb = *(const ulonglong2*)(Wp + k2 * 256 + c0 * 2 + 4);
#pragma unroll
        for (int i = 0; i < 8; i++) {
            unsigned long long ap =
                *(const unsigned long long*)(sA + (ty * 8 + i) * lda + 2 * k2);
            acc[i][0] = fma2(ap, wva.x, acc[i][0]);
            acc[i][1] = fma2(ap, wva.y, acc[i][1]);
            acc[i][2] = fma2(ap, wvb.x, acc[i][2]);
            acc[i][3] = fma2(ap, wvb.y, acc[i][3]);
        }
    }
    float4 bb = *(const float4*)(bias + c0);
    __syncthreads();   // all reads of sA done -> in-place store is safe
#pragma unroll
    for (int i = 0; i < 8; i++) {
        float v[4];
#pragma unroll
        for (int j = 0; j < 4; j++) {
            unsigned long long a = acc[i][j];
            v[j] = __uint_as_float((unsigned)a) + __uint_as_float((unsigned)(a >> 32));
        }
        float v0 = v[0] + bb.x, v1 = v[1] + bb.y, v2 = v[2] + bb.z, v3 = v[3] + bb.w;
        if (relu) {
            v0 = fmaxf(v0, 0.f); v1 = fmaxf(v1, 0.f);
            v2 = fmaxf(v2, 0.f); v3 = fmaxf(v3, 0.f);
        }
        float* o = sOut + (ty * 8 + i) * ldOut + c0;
        o[0] = v0; o[1] = v1; o[2] = v2; o[3] = v3;
    }
}

__global__ __launch_bounds__(128) void mlp_kernel(
    const float* __restrict__ xyz, const float* __restrict__ feats,
    const float* __restrict__ newxyz,
    const float* __restrict__ b1f, const float* __restrict__ b2f,
    const float* __restrict__ b1w, const float* __restrict__ b2w,
    float* __restrict__ fout)
{
    __shared__ float s_a[32 * LDA];    // f_in -> w_in -> h2 (in-place) -> partials
    __shared__ float s_h[32 * 128];    // h1 -> f_prime (in-place)
    __shared__ float s_mean[128];
    __shared__ int   s_g[32];

    const int cid = blockIdx.x;
    const int b = cid >> 10;
    const int tid = threadIdx.x;
    const int tx = tid & 31, ty = tid >> 5;

    if (tid < 32) s_g[tid] = g_gidx[cid * NSAMP + tid];
    __syncthreads();

    const float cx = newxyz[cid * 3 + 0];
    const float cy = newxyz[cid * 3 + 1];
    const float cz = newxyz[cid * 3 + 2];

    if (tid < 32) {
        int g = s_g[tid];
        const float* p = xyz + (b * NPTS + g) * 3;
        s_a[tid * LDA + 0] = p[0] - cx;
        s_a[tid * LDA + 1] = p[1] - cy;
        s_a[tid * LDA + 2] = p[2] - cz;
        s_a[tid * LDA + 67]  = 0.f;    // zero pad col for K=67 pair loop
        s_a[tid * LDA + 131] = 0.f;    // zero pad col for K=131 pair loop
    }
    for (int m = tid; m < 32 * CFEAT; m += 128) {
        int r = m >> 6, c = m & 63;
        s_a[r * LDA + 3 + c] = feats[(b * NPTS + s_g[r]) * CFEAT + c];
    }
    __syncthreads();

    // h1 = relu(f_in @ W1f + b1f)          (s_a -> s_h)
    gemm_tile2(s_a, LDA, K2_1, g_wp + WPO1, b1f, s_h, 128, 1, tx, ty);
    __syncthreads();
    // f' = relu(h1 @ W2f + b2f)            (s_h -> s_h, in place)
    gemm_tile2(s_h, 128, K2_2, g_wp + WPO2, b2f, s_h, 128, 1, tx, ty);
    __syncthreads();

    // mean over the 32 samples
    {
        float sum = 0.f;
        for (int r = 0; r < 32; r++) sum += s_h[r * 128 + tid];
        s_mean[tid] = sum * (1.0f / 32.0f);
    }
    __syncthreads();
    // w_in = [dxyz | f' - mean]  (dxyz already in cols 0..2, col 131 = 0)
    for (int m = tid; m < 32 * 128; m += 128) {
        int r = m >> 7, c = m & 127;
        s_a[r * LDA + 3 + c] = s_h[r * 128 + c] - s_mean[c];
    }
    __syncthreads();

    // h2 = relu(w_in @ W1w + b1w)          (s_a -> s_a, in place)
    gemm_tile2(s_a, LDA, K2_3, g_wp + WPO3, b1w, s_a, LDA, 1, tx, ty);
    __syncthreads();

    // final GEMM + sigmoid + weighted sum fused: alpha = sigmoid(h2 @ W2w + b2w)
    unsigned long long acc[8][4];
#pragma unroll
    for (int i = 0; i < 8; i++)
#pragma unroll
        for (int j = 0; j < 4; j++) acc[i][j] = 0ull;
    const int c0 = tx * 4;
    const float* Wp4 = g_wp + WPO4;
    for (int k2 = 0; k2 < K2_4; k2++) {
        ulonglong2 wva = *(const ulonglong2*)(Wp4 + k2 * 256 + c0 * 2);
        ulonglong2 wvb = *(const ulonglong2*)(Wp4 + k2 * 256 + c0 * 2 + 4);
#pragma unroll
        for (int i = 0; i < 8; i++) {
            unsigned long long ap =
                *(const unsigned long long*)(s_a + (ty * 8 + i) * LDA + 2 * k2);
            acc[i][0] = fma2(ap, wva.x, acc[i][0]);
            acc[i][1] = fma2(ap, wva.y, acc[i][1]);
            acc[i][2] = fma2(ap, wvb.x, acc[i][2]);
            acc[i][3] = fma2(ap, wvb.y, acc[i][3]);
        }
    }
    float4 bb = *(const float4*)(b2w + c0);
    float part0 = 0.f, part1 = 0.f, part2 = 0.f, part3 = 0.f;
#pragma unroll
    for (int i = 0; i < 8; i++) {
        int r = ty * 8 + i;
        float z[4];
#pragma unroll
        for (int j = 0; j < 4; j++) {
            unsigned long long a = acc[i][j];
            z[j] = __uint_as_float((unsigned)a) + __uint_as_float((unsigned)(a >> 32));
        }
        float a0 = 1.0f / (1.0f + __expf(-(z[0] + bb.x)));
        float a1 = 1.0f / (1.0f + __expf(-(z[1] + bb.y)));
        float a2 = 1.0f / (1.0f + __expf(-(z[2] + bb.z)));
        float a3 = 1.0f / (1.0f + __expf(-(z[3] + bb.w)));
        part0 += a0 * s_h[r * 128 + c0 + 0];
        part1 += a1 * s_h[r * 128 + c0 + 1];
        part2 += a2 * s_h[r * 128 + c0 + 2];
        part3 += a3 * s_h[r * 128 + c0 + 3];
    }
    // reduce the 4 warps' partials (reuse s_a; sync before overwrite)
    __syncthreads();
    float* s_part = s_a;
    s_part[ty * 128 + c0 + 0] = part0;
    s_part[ty * 128 + c0 + 1] = part1;
    s_part[ty * 128 + c0 + 2] = part2;
    s_part[ty * 128 + c0 + 3] = part3;
    __syncthreads();
    if (ty == 0) {
        float4 o;
        o.x = s_part[c0 + 0] + s_part[128 + c0 + 0] + s_part[256 + c0 + 0] + s_part[384 + c0 + 0];
        o.y = s_part[c0 + 1] + s_part[128 + c0 + 1] + s_part[256 + c0 + 1] + s_part[384 + c0 + 1];
        o.z = s_part[c0 + 2] + s_part[128 + c0 + 2] + s_part[256 + c0 + 2] + s_part[384 + c0 + 2];
        o.w = s_part[c0 + 3] + s_part[128 + c0 + 3] + s_part[256 + c0 + 3] + s_part[384 + c0 + 3];
        *(float4*)(fout + cid * 128 + c0) = o;
    }
}

// ---------------------------------------------------------------------------

extern "C" void kernel_launch(void* const* d_in, const int* in_sizes, int n_in,
                              void* d_out, int out_size)
{
    const float* xyz   = (const float*)d_in[0];
    const float* feats = (const float*)d_in[1];
    const float* W1f   = (const float*)d_in[2];
    const float* b1f   = (const float*)d_in[3];
    const float* W2f   = (const float*)d_in[4];
    const float* b2f   = (const float*)d_in[5];
    const float* W1w   = (const float*)d_in[6];
    const float* b1w   = (const float*)d_in[7];
    const float* W2w   = (const float*)d_in[8];
    const float* b2w   = (const float*)d_in[9];

    float* out    = (float*)d_out;
    float* newxyz = out;                         // (B, NPOINT, 3)
    float* fout   = out + BATCH * NPOINT * 3;    // (B, NPOINT, HID)

    prep_kernel<<<(228 * 128 + 255) / 256, 256>>>(W1f, W2f, W1w, W2w);
    fps_kernel<<<BATCH, 256>>>(xyz, newxyz);
    group_kernel<<<BATCH * NPOINT, 256>>>(xyz, newxyz);
    mlp_kernel<<<BATCH * NPOINT, 128>>>(
        xyz, feats, newxyz, b1f, b2f, b1w, b2w, fout);
}